// round 15
// baseline (speedup 1.0000x reference)
#include <cuda_runtime.h>
#include <cuda_bf16.h>
#include <cstdint>

// Problem constants (match reference_code)
#define NN   100000
#define C_IN  128
#define C_HID 128
#define C_OUT 64
#define EE   1600000
#define PAD  136                    // bf16 per smem row (272B stride, conflict-free ldmatrix)
#define SPLIT 50048                 // layer-1/2 pipeline split (128-aligned)
#define MAXDEG 64                   // padded slot-CSR row capacity (deg~Poisson(16))

// -------- device scratch (static allocation; no cudaMalloc allowed) --------
__device__ int   g_cnt[NN];
__device__ int   g_cursor[NN];
__device__ float g_dinv[NN];
__device__ uint2 g_csr[(size_t)NN * MAXDEG];       // slot-CSR: {src, w_bits} at dst*MAXDEG+slot
__device__ float g_h1[(size_t)NN * C_HID];
__device__ float g_a1[(size_t)NN * C_HID];
__device__ float g_h2[(size_t)NN * C_OUT];
// W staged as bf16 hi/lo, [n][k] layout, PAD row stride
__device__ __align__(16) __nv_bfloat16 g_w1hi[128 * PAD];
__device__ __align__(16) __nv_bfloat16 g_w1lo[128 * PAD];
__device__ __align__(16) __nv_bfloat16 g_w2hi[64 * PAD];
__device__ __align__(16) __nv_bfloat16 g_w2lo[64 * PAD];

// ---------------------------------------------------------------------------
__device__ __forceinline__ uint32_t smem_u32(const void* p) {
    uint32_t a;
    asm("{ .reg .u64 t; cvta.to.shared.u64 t, %1; cvt.u32.u64 %0, t; }" : "=r"(a) : "l"(p));
    return a;
}
__device__ __forceinline__ void ldm_x4(uint32_t* r, uint32_t addr) {
    asm volatile("ldmatrix.sync.aligned.m8n8.x4.shared.b16 {%0,%1,%2,%3}, [%4];"
                 : "=r"(r[0]), "=r"(r[1]), "=r"(r[2]), "=r"(r[3]) : "r"(addr));
}
__device__ __forceinline__ void mma_bf16(float* c, const uint32_t* a, uint32_t b0, uint32_t b1) {
    asm volatile("mma.sync.aligned.m16n8k16.row.col.f32.bf16.bf16.f32 "
                 "{%0,%1,%2,%3}, {%4,%5,%6,%7}, {%8,%9}, {%0,%1,%2,%3};"
                 : "+f"(c[0]), "+f"(c[1]), "+f"(c[2]), "+f"(c[3])
                 : "r"(a[0]), "r"(a[1]), "r"(a[2]), "r"(a[3]), "r"(b0), "r"(b1));
}
__device__ __forceinline__ void cvt_pair(float x, float y, uint32_t& hi, uint32_t& lo) {
    __nv_bfloat16 hx = __float2bfloat16_rn(x);
    __nv_bfloat16 hy = __float2bfloat16_rn(y);
    __nv_bfloat16 lx = __float2bfloat16_rn(x - __bfloat162float(hx));
    __nv_bfloat16 ly = __float2bfloat16_rn(y - __bfloat162float(hy));
    hi = ((uint32_t)__bfloat16_as_ushort(hy) << 16) | __bfloat16_as_ushort(hx);
    lo = ((uint32_t)__bfloat16_as_ushort(ly) << 16) | __bfloat16_as_ushort(lx);
}

// ---------------------------------------------------------------------------
__global__ void k_zero() {
    int i = blockIdx.x * blockDim.x + threadIdx.x;
    if (i < NN) {
        g_cnt[i] = 0;
        g_cursor[i] = 0;
    }
}
__global__ void k_count(const int* __restrict__ ei) {
    int e = blockIdx.x * blockDim.x + threadIdx.x;
    if (e >= EE) return;
    atomicAdd(&g_cnt[ei[EE + e]], 1);
}
__global__ void k_dinv() {
    int i = blockIdx.x * blockDim.x + threadIdx.x;
    if (i < NN) g_dinv[i] = rsqrtf(1.0f + (float)g_cnt[i]);
}
// slot placement: no prefix scan needed; row start is dst*MAXDEG.
__global__ void k_place(const int* __restrict__ ei) {
    int e = blockIdx.x * blockDim.x + threadIdx.x;
    if (e >= EE) return;
    int s = ei[e];
    int d = ei[EE + e];
    int pos = atomicAdd(&g_cursor[d], 1);
    if (pos < MAXDEG) {
        uint2 pk;
        pk.x = (uint32_t)s;
        pk.y = __float_as_uint(g_dinv[s] * g_dinv[d]);
        g_csr[(size_t)d * MAXDEG + pos] = pk;
    }
}

// ---------------------------------------------------------------------------
// Prep: W [k][n] row-major -> [n][k] bf16 hi/lo with PAD stride.
__global__ void k_prep_w1(const float* __restrict__ W1) {
    int idx = blockIdx.x * blockDim.x + threadIdx.x;
    if (idx >= 128 * 128) return;
    int k = idx >> 7;
    int n = idx & 127;
    float w = W1[idx];
    __nv_bfloat16 hi = __float2bfloat16_rn(w);
    __nv_bfloat16 lo = __float2bfloat16_rn(w - __bfloat162float(hi));
    g_w1hi[n * PAD + k] = hi;
    g_w1lo[n * PAD + k] = lo;
}
__global__ void k_prep_w2(const float* __restrict__ W2) {
    int idx = blockIdx.x * blockDim.x + threadIdx.x;
    if (idx >= 128 * 64) return;
    int k = idx >> 6;
    int n = idx & 63;
    float w = W2[idx];
    __nv_bfloat16 hi = __float2bfloat16_rn(w);
    __nv_bfloat16 lo = __float2bfloat16_rn(w - __bfloat162float(hi));
    g_w2hi[n * PAD + k] = hi;
    g_w2lo[n * PAD + k] = lo;
}

// ---------------------------------------------------------------------------
// GEMM1 (tensor): h1[128xCTA,128] = x @ W1, split-bf16 3-pass HMMA.
#define SM1_TOTAL (4 * 128 * PAD * 2)
__global__ void __launch_bounds__(256, 1) k_gemm1_mma(const float* __restrict__ A) {
    extern __shared__ __nv_bfloat16 sm[];
    __nv_bfloat16* Ahi = sm;
    __nv_bfloat16* Alo = sm + 128 * PAD;
    __nv_bfloat16* Bhi = sm + 2 * 128 * PAD;
    __nv_bfloat16* Blo = sm + 3 * 128 * PAD;
    const int tid  = threadIdx.x;
    const int row0 = blockIdx.x * 128;

    {
        const uint4* shi = (const uint4*)g_w1hi;
        const uint4* slo = (const uint4*)g_w1lo;
        uint4* dhi = (uint4*)Bhi;
        uint4* dlo = (uint4*)Blo;
        #pragma unroll
        for (int i = tid; i < 128 * PAD * 2 / 16; i += 256) {
            dhi[i] = shi[i];
            dlo[i] = slo[i];
        }
    }
    {
        int r  = tid >> 1;
        int k0 = (tid & 1) * 64;
        int row = row0 + r;
        if (row >= NN) row = NN - 1;
        const float4* xr = (const float4*)(A + (size_t)row * 128 + k0);
        uint32_t* dh = (uint32_t*)(Ahi + r * PAD + k0);
        uint32_t* dl = (uint32_t*)(Alo + r * PAD + k0);
        #pragma unroll
        for (int q = 0; q < 16; q++) {
            float4 v = xr[q];
            uint32_t h0, l0, h1, l1;
            cvt_pair(v.x, v.y, h0, l0);
            cvt_pair(v.z, v.w, h1, l1);
            dh[q * 2]     = h0;
            dh[q * 2 + 1] = h1;
            dl[q * 2]     = l0;
            dl[q * 2 + 1] = l1;
        }
    }
    __syncthreads();

    const int lid = tid & 31, wid = tid >> 5;
    const int wm = wid & 3, wn = wid >> 2;
    const int lr = lid & 7, lb = lid >> 3;

    float c[2][8][4];
    #pragma unroll
    for (int mt = 0; mt < 2; mt++)
        #pragma unroll
        for (int nt = 0; nt < 8; nt++)
            #pragma unroll
            for (int q = 0; q < 4; q++) c[mt][nt][q] = 0.f;

    #pragma unroll
    for (int p = 0; p < 3; p++) {
        const __nv_bfloat16* At = (p == 2) ? Alo : Ahi;
        const __nv_bfloat16* Bt = (p == 1) ? Blo : Bhi;
        #pragma unroll
        for (int ks = 0; ks < 8; ks++) {
            uint32_t a[2][4];
            #pragma unroll
            for (int mt = 0; mt < 2; mt++) {
                int arow = wm * 32 + mt * 16 + (lb & 1) * 8 + lr;
                int ak   = ks * 16 + (lb >> 1) * 8;
                ldm_x4(a[mt], smem_u32(At + arow * PAD + ak));
            }
            #pragma unroll
            for (int np = 0; np < 4; np++) {
                uint32_t b[4];
                int brow = wn * 64 + np * 16 + (lb >> 1) * 8 + lr;
                int bk   = ks * 16 + (lb & 1) * 8;
                ldm_x4(b, smem_u32(Bt + brow * PAD + bk));
                #pragma unroll
                for (int mt = 0; mt < 2; mt++) {
                    mma_bf16(c[mt][np * 2],     a[mt], b[0], b[1]);
                    mma_bf16(c[mt][np * 2 + 1], a[mt], b[2], b[3]);
                }
            }
        }
    }

    const int g = lid >> 2, tg = lid & 3;
    #pragma unroll
    for (int mt = 0; mt < 2; mt++) {
        int r0 = row0 + wm * 32 + mt * 16 + g;
        #pragma unroll
        for (int nt = 0; nt < 8; nt++) {
            int col = wn * 64 + nt * 8 + tg * 2;
            if (r0 < NN)
                *(float2*)(g_h1 + (size_t)r0 * 128 + col) = make_float2(c[mt][nt][0], c[mt][nt][1]);
            if (r0 + 8 < NN)
                *(float2*)(g_h1 + (size_t)(r0 + 8) * 128 + col) = make_float2(c[mt][nt][2], c[mt][nt][3]);
        }
    }
}

// GEMM2 (tensor): h2 = relu(a1) @ W2, split-bf16 3-pass HMMA; row_base for pipelining.
#define SM2_TOTAL (2 * 128 * PAD * 2 + 2 * 64 * PAD * 2)
__global__ void __launch_bounds__(256, 1) k_gemm2_mma(int row_base) {
    extern __shared__ __nv_bfloat16 sm[];
    __nv_bfloat16* Ahi = sm;
    __nv_bfloat16* Alo = sm + 128 * PAD;
    __nv_bfloat16* Bhi = sm + 2 * 128 * PAD;
    __nv_bfloat16* Blo = sm + 2 * 128 * PAD + 64 * PAD;
    const int tid  = threadIdx.x;
    const int row0 = row_base + blockIdx.x * 128;

    {
        const uint4* shi = (const uint4*)g_w2hi;
        const uint4* slo = (const uint4*)g_w2lo;
        uint4* dhi = (uint4*)Bhi;
        uint4* dlo = (uint4*)Blo;
        #pragma unroll
        for (int i = tid; i < 64 * PAD * 2 / 16; i += 256) {
            dhi[i] = shi[i];
            dlo[i] = slo[i];
        }
    }
    {
        int r  = tid >> 1;
        int k0 = (tid & 1) * 64;
        int row = row0 + r;
        if (row >= NN) row = NN - 1;
        const float4* xr = (const float4*)(g_a1 + (size_t)row * 128 + k0);
        uint32_t* dh = (uint32_t*)(Ahi + r * PAD + k0);
        uint32_t* dl = (uint32_t*)(Alo + r * PAD + k0);
        #pragma unroll
        for (int q = 0; q < 16; q++) {
            float4 v = xr[q];
            v.x = fmaxf(v.x, 0.f); v.y = fmaxf(v.y, 0.f);
            v.z = fmaxf(v.z, 0.f); v.w = fmaxf(v.w, 0.f);
            uint32_t h0, l0, h1, l1;
            cvt_pair(v.x, v.y, h0, l0);
            cvt_pair(v.z, v.w, h1, l1);
            dh[q * 2]     = h0;
            dh[q * 2 + 1] = h1;
            dl[q * 2]     = l0;
            dl[q * 2 + 1] = l1;
        }
    }
    __syncthreads();

    const int lid = tid & 31, wid = tid >> 5;
    const int wm = wid & 3, wn = wid >> 2;
    const int lr = lid & 7, lb = lid >> 3;

    float c[2][4][4];
    #pragma unroll
    for (int mt = 0; mt < 2; mt++)
        #pragma unroll
        for (int nt = 0; nt < 4; nt++)
            #pragma unroll
            for (int q = 0; q < 4; q++) c[mt][nt][q] = 0.f;

    #pragma unroll
    for (int p = 0; p < 3; p++) {
        const __nv_bfloat16* At = (p == 2) ? Alo : Ahi;
        const __nv_bfloat16* Bt = (p == 1) ? Blo : Bhi;
        #pragma unroll
        for (int ks = 0; ks < 8; ks++) {
            uint32_t a[2][4];
            #pragma unroll
            for (int mt = 0; mt < 2; mt++) {
                int arow = wm * 32 + mt * 16 + (lb & 1) * 8 + lr;
                int ak   = ks * 16 + (lb >> 1) * 8;
                ldm_x4(a[mt], smem_u32(At + arow * PAD + ak));
            }
            #pragma unroll
            for (int np = 0; np < 2; np++) {
                uint32_t b[4];
                int brow = wn * 32 + np * 16 + (lb >> 1) * 8 + lr;
                int bk   = ks * 16 + (lb & 1) * 8;
                ldm_x4(b, smem_u32(Bt + brow * PAD + bk));
                #pragma unroll
                for (int mt = 0; mt < 2; mt++) {
                    mma_bf16(c[mt][np * 2],     a[mt], b[0], b[1]);
                    mma_bf16(c[mt][np * 2 + 1], a[mt], b[2], b[3]);
                }
            }
        }
    }

    const int g = lid >> 2, tg = lid & 3;
    #pragma unroll
    for (int mt = 0; mt < 2; mt++) {
        int r0 = row0 + wm * 32 + mt * 16 + g;
        #pragma unroll
        for (int nt = 0; nt < 4; nt++) {
            int col = wn * 32 + nt * 8 + tg * 2;
            if (r0 < NN)
                *(float2*)(g_h2 + (size_t)r0 * 64 + col) = make_float2(c[mt][nt][0], c[mt][nt][1]);
            if (r0 + 8 < NN)
                *(float2*)(g_h2 + (size_t)(r0 + 8) * 64 + col) = make_float2(c[mt][nt][2], c[mt][nt][3]);
        }
    }
}

// ---------------------------------------------------------------------------
// Layer-1 aggregation: warp per dst node (float4/lane), slot-CSR rows.
__global__ void k_agg1(const float* __restrict__ b1, int base, int end) {
    int t = blockIdx.x * blockDim.x + threadIdx.x;
    int i = base + (t >> 5);
    if (i >= end) return;
    int j4 = (t & 31) * 4;

    float di = g_dinv[i];
    float ss = di * di;
    float4 h = *(const float4*)(g_h1 + (size_t)i * 128 + j4);
    float4 b = *(const float4*)(b1 + j4);
    float4 acc = make_float4(h.x * ss + b.x, h.y * ss + b.y,
                             h.z * ss + b.z, h.w * ss + b.w);

    const uint2* row = g_csr + (size_t)i * MAXDEG;
    int deg = g_cnt[i];
    if (deg > MAXDEG) deg = MAXDEG;
    for (int k = 0; k < deg; k++) {
        uint2 pk = row[k];
        float w  = __uint_as_float(pk.y);
        float4 v = *(const float4*)(g_h1 + (size_t)pk.x * 128 + j4);
        acc.x += w * v.x;
        acc.y += w * v.y;
        acc.z += w * v.z;
        acc.w += w * v.w;
    }
    *(float4*)(g_a1 + (size_t)i * 128 + j4) = acc;
}

// Layer-2 aggregation: warp per dst node (float2/lane) -> no half-warp divergence.
__global__ void k_agg2(const float* __restrict__ b2, float* __restrict__ out) {
    int t = blockIdx.x * blockDim.x + threadIdx.x;
    int i = t >> 5;
    if (i >= NN) return;
    int j2 = (t & 31) * 2;

    float di = g_dinv[i];
    float ss = di * di;
    float2 h = *(const float2*)(g_h2 + (size_t)i * 64 + j2);
    float2 b = *(const float2*)(b2 + j2);
    float2 acc = make_float2(h.x * ss + b.x, h.y * ss + b.y);

    const uint2* row = g_csr + (size_t)i * MAXDEG;
    int deg = g_cnt[i];
    if (deg > MAXDEG) deg = MAXDEG;
    for (int k = 0; k < deg; k++) {
        uint2 pk = row[k];
        float w  = __uint_as_float(pk.y);
        float2 v = *(const float2*)(g_h2 + (size_t)pk.x * 64 + j2);
        acc.x += w * v.x;
        acc.y += w * v.y;
    }
    *(float2*)(out + (size_t)i * 64 + j2) = acc;
}

// ---------------------------------------------------------------------------
extern "C" void kernel_launch(void* const* d_in, const int* in_sizes, int n_in,
                              void* d_out, int out_size) {
    const float* x  = (const float*)d_in[0];
    const int*   ei = (const int*)d_in[1];     // int32 (JAX x64 disabled)
    const float* W1 = (const float*)d_in[2];
    const float* b1 = (const float*)d_in[3];
    const float* W2 = (const float*)d_in[4];
    const float* b2 = (const float*)d_in[5];
    float* out = (float*)d_out;

    const int T = 256;
    const int NB = (NN + T - 1) / T;

    static cudaStream_t s2 = nullptr;
    static cudaEvent_t evF = nullptr, evCSR = nullptr, evA0 = nullptr, evG2a = nullptr;
    if (s2 == nullptr) {
        cudaStreamCreateWithFlags(&s2, cudaStreamNonBlocking);
        cudaEventCreateWithFlags(&evF, cudaEventDisableTiming);
        cudaEventCreateWithFlags(&evCSR, cudaEventDisableTiming);
        cudaEventCreateWithFlags(&evA0, cudaEventDisableTiming);
        cudaEventCreateWithFlags(&evG2a, cudaEventDisableTiming);
        cudaFuncSetAttribute(k_gemm1_mma, cudaFuncAttributeMaxDynamicSharedMemorySize, SM1_TOTAL);
        cudaFuncSetAttribute(k_gemm2_mma, cudaFuncAttributeMaxDynamicSharedMemorySize, SM2_TOTAL);
    }

    // fork: s2 builds slot-CSR (no scan); main preps W + runs GEMM1
    cudaEventRecord(evF, 0);
    cudaStreamWaitEvent(s2, evF, 0);

    k_zero<<<NB, T, 0, s2>>>();
    k_count<<<(EE + T - 1) / T, T, 0, s2>>>(ei);
    k_dinv<<<NB, T, 0, s2>>>();
    k_place<<<(EE + T - 1) / T, T, 0, s2>>>(ei);
    cudaEventRecord(evCSR, s2);

    k_prep_w1<<<(128 * 128 + T - 1) / T, T>>>(W1);
    k_prep_w2<<<(128 * 64 + T - 1) / T, T>>>(W2);
    k_gemm1_mma<<<(NN + 127) / 128, T, SM1_TOTAL>>>(x);

    // join CSR, then pipelined layer-1 aggregation / layer-2 GEMM
    cudaStreamWaitEvent(0, evCSR, 0);
    k_agg1<<<(SPLIT * 32 + T - 1) / T, T>>>(b1, 0, SPLIT);                 // half 0
    cudaEventRecord(evA0, 0);

    // s2: gemm2 on half 0 while main aggregates half 1
    cudaStreamWaitEvent(s2, evA0, 0);
    k_gemm2_mma<<<SPLIT / 128, T, SM2_TOTAL, s2>>>(0);
    cudaEventRecord(evG2a, s2);

    k_agg1<<<((NN - SPLIT) * 32 + T - 1) / T, T>>>(b1, SPLIT, NN);         // half 1
    k_gemm2_mma<<<(NN - SPLIT + 127) / 128, T, SM2_TOTAL>>>(SPLIT);

    // join gemm2 half 0, final aggregation into d_out
    cudaStreamWaitEvent(0, evG2a, 0);
    k_agg2<<<((size_t)NN * 32 + T - 1) / T, T>>>(b2, out);
}

// round 16
// speedup vs baseline: 1.0757x; 1.0757x over previous
#include <cuda_runtime.h>
#include <cuda_bf16.h>
#include <cstdint>

// Problem constants (match reference_code)
#define NN   100000
#define C_IN  128
#define C_HID 128
#define C_OUT 64
#define EE   1600000
#define NBLK ((NN + 255) / 256)     // 391 scan blocks
#define PAD  136                    // bf16 per smem row (272B stride, conflict-free ldmatrix)
#define SPLIT 50048                 // layer-1/2 pipeline split (128-aligned)

// -------- device scratch (static allocation; no cudaMalloc allowed) --------
__device__ int   g_cnt[NN];
__device__ float g_dinv[NN];
__device__ int   g_row[NN];
__device__ int   g_cursor[NN];
__device__ int   g_bsum[NBLK];
__device__ int   g_boff[NBLK];
__device__ uint2 g_csr[EE];                        // packed {src, w_bits}, compact CSR
__device__ float g_h1[(size_t)NN * C_HID];
__device__ float g_a1[(size_t)NN * C_HID];
__device__ float g_h2[(size_t)NN * C_OUT];
// W staged as bf16 hi/lo, [n][k] layout, PAD row stride
__device__ __align__(16) __nv_bfloat16 g_w1hi[128 * PAD];
__device__ __align__(16) __nv_bfloat16 g_w1lo[128 * PAD];
__device__ __align__(16) __nv_bfloat16 g_w2hi[64 * PAD];
__device__ __align__(16) __nv_bfloat16 g_w2lo[64 * PAD];

// ---------------------------------------------------------------------------
__device__ __forceinline__ uint32_t smem_u32(const void* p) {
    uint32_t a;
    asm("{ .reg .u64 t; cvta.to.shared.u64 t, %1; cvt.u32.u64 %0, t; }" : "=r"(a) : "l"(p));
    return a;
}
__device__ __forceinline__ void ldm_x4(uint32_t* r, uint32_t addr) {
    asm volatile("ldmatrix.sync.aligned.m8n8.x4.shared.b16 {%0,%1,%2,%3}, [%4];"
                 : "=r"(r[0]), "=r"(r[1]), "=r"(r[2]), "=r"(r[3]) : "r"(addr));
}
__device__ __forceinline__ void mma_bf16(float* c, const uint32_t* a, uint32_t b0, uint32_t b1) {
    asm volatile("mma.sync.aligned.m16n8k16.row.col.f32.bf16.bf16.f32 "
                 "{%0,%1,%2,%3}, {%4,%5,%6,%7}, {%8,%9}, {%0,%1,%2,%3};"
                 : "+f"(c[0]), "+f"(c[1]), "+f"(c[2]), "+f"(c[3])
                 : "r"(a[0]), "r"(a[1]), "r"(a[2]), "r"(a[3]), "r"(b0), "r"(b1));
}
__device__ __forceinline__ void cvt_pair(float x, float y, uint32_t& hi, uint32_t& lo) {
    __nv_bfloat16 hx = __float2bfloat16_rn(x);
    __nv_bfloat16 hy = __float2bfloat16_rn(y);
    __nv_bfloat16 lx = __float2bfloat16_rn(x - __bfloat162float(hx));
    __nv_bfloat16 ly = __float2bfloat16_rn(y - __bfloat162float(hy));
    hi = ((uint32_t)__bfloat16_as_ushort(hy) << 16) | __bfloat16_as_ushort(hx);
    lo = ((uint32_t)__bfloat16_as_ushort(ly) << 16) | __bfloat16_as_ushort(lx);
}

// ---------------------------------------------------------------------------
__global__ void k_zero_cnt() {
    int i = blockIdx.x * blockDim.x + threadIdx.x;
    if (i < NN) g_cnt[i] = 0;
}
__global__ void k_count(const int* __restrict__ ei) {
    int e = blockIdx.x * blockDim.x + threadIdx.x;
    if (e >= EE) return;
    atomicAdd(&g_cnt[ei[EE + e]], 1);
}
__global__ void k_scan_block() {
    __shared__ int sdata[256];
    int i = blockIdx.x * 256 + threadIdx.x;
    int v = (i < NN) ? g_cnt[i] : 0;
    sdata[threadIdx.x] = v;
    __syncthreads();
    #pragma unroll
    for (int off = 1; off < 256; off <<= 1) {
        int t = (threadIdx.x >= off) ? sdata[threadIdx.x - off] : 0;
        __syncthreads();
        sdata[threadIdx.x] += t;
        __syncthreads();
    }
    if (i < NN) g_row[i] = sdata[threadIdx.x] - v;
    if (threadIdx.x == 255) g_bsum[blockIdx.x] = sdata[255];
}
__global__ void k_scan_bsums() {
    __shared__ int sdata[512];
    int v = (threadIdx.x < NBLK) ? g_bsum[threadIdx.x] : 0;
    sdata[threadIdx.x] = v;
    __syncthreads();
    #pragma unroll
    for (int off = 1; off < 512; off <<= 1) {
        int t = (threadIdx.x >= off) ? sdata[threadIdx.x - off] : 0;
        __syncthreads();
        sdata[threadIdx.x] += t;
        __syncthreads();
    }
    if (threadIdx.x < NBLK) g_boff[threadIdx.x] = sdata[threadIdx.x] - v;
}
// scan finalize + dinv fused
__global__ void k_scan_add() {
    int i = blockIdx.x * 256 + threadIdx.x;
    if (i >= NN) return;
    int r = g_row[i] + g_boff[blockIdx.x];
    g_row[i] = r;
    g_cursor[i] = r;
    g_dinv[i] = rsqrtf(1.0f + (float)g_cnt[i]);
}
__global__ void k_reorder(const int* __restrict__ ei) {
    int e = blockIdx.x * blockDim.x + threadIdx.x;
    if (e >= EE) return;
    int s = ei[e];
    int d = ei[EE + e];
    int pos = atomicAdd(&g_cursor[d], 1);
    uint2 pk;
    pk.x = (uint32_t)s;
    pk.y = __float_as_uint(g_dinv[s] * g_dinv[d]);
    g_csr[pos] = pk;
}

// ---------------------------------------------------------------------------
// Merged prep: W1 [k][n] and W2 [k][n] row-major -> [n][k] bf16 hi/lo, PAD stride.
__global__ void k_prep_w(const float* __restrict__ W1, const float* __restrict__ W2) {
    int idx = blockIdx.x * blockDim.x + threadIdx.x;
    if (idx < 128 * 128) {
        int k = idx >> 7;
        int n = idx & 127;
        float w = W1[idx];
        __nv_bfloat16 hi = __float2bfloat16_rn(w);
        __nv_bfloat16 lo = __float2bfloat16_rn(w - __bfloat162float(hi));
        g_w1hi[n * PAD + k] = hi;
        g_w1lo[n * PAD + k] = lo;
    } else if (idx < 128 * 128 + 128 * 64) {
        int j = idx - 128 * 128;
        int k = j >> 6;
        int n = j & 63;
        float w = W2[j];
        __nv_bfloat16 hi = __float2bfloat16_rn(w);
        __nv_bfloat16 lo = __float2bfloat16_rn(w - __bfloat162float(hi));
        g_w2hi[n * PAD + k] = hi;
        g_w2lo[n * PAD + k] = lo;
    }
}

// ---------------------------------------------------------------------------
// GEMM1 (tensor): h1[128xCTA,128] = x @ W1, split-bf16 3-pass HMMA.
#define SM1_TOTAL (4 * 128 * PAD * 2)
__global__ void __launch_bounds__(256, 1) k_gemm1_mma(const float* __restrict__ A) {
    extern __shared__ __nv_bfloat16 sm[];
    __nv_bfloat16* Ahi = sm;
    __nv_bfloat16* Alo = sm + 128 * PAD;
    __nv_bfloat16* Bhi = sm + 2 * 128 * PAD;
    __nv_bfloat16* Blo = sm + 3 * 128 * PAD;
    const int tid  = threadIdx.x;
    const int row0 = blockIdx.x * 128;

    {
        const uint4* shi = (const uint4*)g_w1hi;
        const uint4* slo = (const uint4*)g_w1lo;
        uint4* dhi = (uint4*)Bhi;
        uint4* dlo = (uint4*)Blo;
        #pragma unroll
        for (int i = tid; i < 128 * PAD * 2 / 16; i += 256) {
            dhi[i] = shi[i];
            dlo[i] = slo[i];
        }
    }
    {
        int r  = tid >> 1;
        int k0 = (tid & 1) * 64;
        int row = row0 + r;
        if (row >= NN) row = NN - 1;
        const float4* xr = (const float4*)(A + (size_t)row * 128 + k0);
        uint32_t* dh = (uint32_t*)(Ahi + r * PAD + k0);
        uint32_t* dl = (uint32_t*)(Alo + r * PAD + k0);
        #pragma unroll
        for (int q = 0; q < 16; q++) {
            float4 v = xr[q];
            uint32_t h0, l0, h1, l1;
            cvt_pair(v.x, v.y, h0, l0);
            cvt_pair(v.z, v.w, h1, l1);
            dh[q * 2]     = h0;
            dh[q * 2 + 1] = h1;
            dl[q * 2]     = l0;
            dl[q * 2 + 1] = l1;
        }
    }
    __syncthreads();

    const int lid = tid & 31, wid = tid >> 5;
    const int wm = wid & 3, wn = wid >> 2;
    const int lr = lid & 7, lb = lid >> 3;

    float c[2][8][4];
    #pragma unroll
    for (int mt = 0; mt < 2; mt++)
        #pragma unroll
        for (int nt = 0; nt < 8; nt++)
            #pragma unroll
            for (int q = 0; q < 4; q++) c[mt][nt][q] = 0.f;

    #pragma unroll
    for (int p = 0; p < 3; p++) {
        const __nv_bfloat16* At = (p == 2) ? Alo : Ahi;
        const __nv_bfloat16* Bt = (p == 1) ? Blo : Bhi;
        #pragma unroll
        for (int ks = 0; ks < 8; ks++) {
            uint32_t a[2][4];
            #pragma unroll
            for (int mt = 0; mt < 2; mt++) {
                int arow = wm * 32 + mt * 16 + (lb & 1) * 8 + lr;
                int ak   = ks * 16 + (lb >> 1) * 8;
                ldm_x4(a[mt], smem_u32(At + arow * PAD + ak));
            }
            #pragma unroll
            for (int np = 0; np < 4; np++) {
                uint32_t b[4];
                int brow = wn * 64 + np * 16 + (lb >> 1) * 8 + lr;
                int bk   = ks * 16 + (lb & 1) * 8;
                ldm_x4(b, smem_u32(Bt + brow * PAD + bk));
                #pragma unroll
                for (int mt = 0; mt < 2; mt++) {
                    mma_bf16(c[mt][np * 2],     a[mt], b[0], b[1]);
                    mma_bf16(c[mt][np * 2 + 1], a[mt], b[2], b[3]);
                }
            }
        }
    }

    const int g = lid >> 2, tg = lid & 3;
    #pragma unroll
    for (int mt = 0; mt < 2; mt++) {
        int r0 = row0 + wm * 32 + mt * 16 + g;
        #pragma unroll
        for (int nt = 0; nt < 8; nt++) {
            int col = wn * 64 + nt * 8 + tg * 2;
            if (r0 < NN)
                *(float2*)(g_h1 + (size_t)r0 * 128 + col) = make_float2(c[mt][nt][0], c[mt][nt][1]);
            if (r0 + 8 < NN)
                *(float2*)(g_h1 + (size_t)(r0 + 8) * 128 + col) = make_float2(c[mt][nt][2], c[mt][nt][3]);
        }
    }
}

// GEMM2 (tensor): h2 = relu(a1) @ W2, split-bf16 3-pass HMMA; row_base for pipelining.
#define SM2_TOTAL (2 * 128 * PAD * 2 + 2 * 64 * PAD * 2)
__global__ void __launch_bounds__(256, 1) k_gemm2_mma(int row_base) {
    extern __shared__ __nv_bfloat16 sm[];
    __nv_bfloat16* Ahi = sm;
    __nv_bfloat16* Alo = sm + 128 * PAD;
    __nv_bfloat16* Bhi = sm + 2 * 128 * PAD;
    __nv_bfloat16* Blo = sm + 2 * 128 * PAD + 64 * PAD;
    const int tid  = threadIdx.x;
    const int row0 = row_base + blockIdx.x * 128;

    {
        const uint4* shi = (const uint4*)g_w2hi;
        const uint4* slo = (const uint4*)g_w2lo;
        uint4* dhi = (uint4*)Bhi;
        uint4* dlo = (uint4*)Blo;
        #pragma unroll
        for (int i = tid; i < 64 * PAD * 2 / 16; i += 256) {
            dhi[i] = shi[i];
            dlo[i] = slo[i];
        }
    }
    {
        int r  = tid >> 1;
        int k0 = (tid & 1) * 64;
        int row = row0 + r;
        if (row >= NN) row = NN - 1;
        const float4* xr = (const float4*)(g_a1 + (size_t)row * 128 + k0);
        uint32_t* dh = (uint32_t*)(Ahi + r * PAD + k0);
        uint32_t* dl = (uint32_t*)(Alo + r * PAD + k0);
        #pragma unroll
        for (int q = 0; q < 16; q++) {
            float4 v = xr[q];
            v.x = fmaxf(v.x, 0.f); v.y = fmaxf(v.y, 0.f);
            v.z = fmaxf(v.z, 0.f); v.w = fmaxf(v.w, 0.f);
            uint32_t h0, l0, h1, l1;
            cvt_pair(v.x, v.y, h0, l0);
            cvt_pair(v.z, v.w, h1, l1);
            dh[q * 2]     = h0;
            dh[q * 2 + 1] = h1;
            dl[q * 2]     = l0;
            dl[q * 2 + 1] = l1;
        }
    }
    __syncthreads();

    const int lid = tid & 31, wid = tid >> 5;
    const int wm = wid & 3, wn = wid >> 2;
    const int lr = lid & 7, lb = lid >> 3;

    float c[2][4][4];
    #pragma unroll
    for (int mt = 0; mt < 2; mt++)
        #pragma unroll
        for (int nt = 0; nt < 4; nt++)
            #pragma unroll
            for (int q = 0; q < 4; q++) c[mt][nt][q] = 0.f;

    #pragma unroll
    for (int p = 0; p < 3; p++) {
        const __nv_bfloat16* At = (p == 2) ? Alo : Ahi;
        const __nv_bfloat16* Bt = (p == 1) ? Blo : Bhi;
        #pragma unroll
        for (int ks = 0; ks < 8; ks++) {
            uint32_t a[2][4];
            #pragma unroll
            for (int mt = 0; mt < 2; mt++) {
                int arow = wm * 32 + mt * 16 + (lb & 1) * 8 + lr;
                int ak   = ks * 16 + (lb >> 1) * 8;
                ldm_x4(a[mt], smem_u32(At + arow * PAD + ak));
            }
            #pragma unroll
            for (int np = 0; np < 2; np++) {
                uint32_t b[4];
                int brow = wn * 32 + np * 16 + (lb >> 1) * 8 + lr;
                int bk   = ks * 16 + (lb & 1) * 8;
                ldm_x4(b, smem_u32(Bt + brow * PAD + bk));
                #pragma unroll
                for (int mt = 0; mt < 2; mt++) {
                    mma_bf16(c[mt][np * 2],     a[mt], b[0], b[1]);
                    mma_bf16(c[mt][np * 2 + 1], a[mt], b[2], b[3]);
                }
            }
        }
    }

    const int g = lid >> 2, tg = lid & 3;
    #pragma unroll
    for (int mt = 0; mt < 2; mt++) {
        int r0 = row0 + wm * 32 + mt * 16 + g;
        #pragma unroll
        for (int nt = 0; nt < 4; nt++) {
            int col = wn * 32 + nt * 8 + tg * 2;
            if (r0 < NN)
                *(float2*)(g_h2 + (size_t)r0 * 64 + col) = make_float2(c[mt][nt][0], c[mt][nt][1]);
            if (r0 + 8 < NN)
                *(float2*)(g_h2 + (size_t)(r0 + 8) * 64 + col) = make_float2(c[mt][nt][2], c[mt][nt][3]);
        }
    }
}

// ---------------------------------------------------------------------------
// Aggregations over [base, end) node range (packed compact CSR).
__global__ void k_agg1(const float* __restrict__ b1, int base, int end) {
    int t = blockIdx.x * blockDim.x + threadIdx.x;
    int i = base + (t >> 5);
    if (i >= end) return;
    int j4 = (t & 31) * 4;

    float di = g_dinv[i];
    float ss = di * di;
    float4 h = *(const float4*)(g_h1 + (size_t)i * 128 + j4);
    float4 b = *(const float4*)(b1 + j4);
    float4 acc = make_float4(h.x * ss + b.x, h.y * ss + b.y,
                             h.z * ss + b.z, h.w * ss + b.w);

    int start = g_row[i];
    int stop  = start + g_cnt[i];
    for (int k = start; k < stop; k++) {
        uint2 pk = g_csr[k];
        float w  = __uint_as_float(pk.y);
        float4 v = *(const float4*)(g_h1 + (size_t)pk.x * 128 + j4);
        acc.x += w * v.x;
        acc.y += w * v.y;
        acc.z += w * v.z;
        acc.w += w * v.w;
    }
    *(float4*)(g_a1 + (size_t)i * 128 + j4) = acc;
}

__global__ void k_agg2(const float* __restrict__ b2, float* __restrict__ out) {
    int t = blockIdx.x * blockDim.x + threadIdx.x;
    int i = t >> 4;
    if (i >= NN) return;
    int j4 = (t & 15) * 4;

    float di = g_dinv[i];
    float ss = di * di;
    float4 h = *(const float4*)(g_h2 + (size_t)i * 64 + j4);
    float4 b = *(const float4*)(b2 + j4);
    float4 acc = make_float4(h.x * ss + b.x, h.y * ss + b.y,
                             h.z * ss + b.z, h.w * ss + b.w);

    int start = g_row[i];
    int stop  = start + g_cnt[i];
    for (int k = start; k < stop; k++) {
        uint2 pk = g_csr[k];
        float w  = __uint_as_float(pk.y);
        float4 v = *(const float4*)(g_h2 + (size_t)pk.x * 64 + j4);
        acc.x += w * v.x;
        acc.y += w * v.y;
        acc.z += w * v.z;
        acc.w += w * v.w;
    }
    *(float4*)(out + (size_t)i * 64 + j4) = acc;
}

// ---------------------------------------------------------------------------
extern "C" void kernel_launch(void* const* d_in, const int* in_sizes, int n_in,
                              void* d_out, int out_size) {
    const float* x  = (const float*)d_in[0];
    const int*   ei = (const int*)d_in[1];     // int32 (JAX x64 disabled)
    const float* W1 = (const float*)d_in[2];
    const float* b1 = (const float*)d_in[3];
    const float* W2 = (const float*)d_in[4];
    const float* b2 = (const float*)d_in[5];
    float* out = (float*)d_out;

    const int T = 256;

    static cudaStream_t s2 = nullptr;
    static cudaEvent_t evF = nullptr, evCSR = nullptr, evA0 = nullptr, evG2a = nullptr;
    if (s2 == nullptr) {
        cudaStreamCreateWithFlags(&s2, cudaStreamNonBlocking);
        cudaEventCreateWithFlags(&evF, cudaEventDisableTiming);
        cudaEventCreateWithFlags(&evCSR, cudaEventDisableTiming);
        cudaEventCreateWithFlags(&evA0, cudaEventDisableTiming);
        cudaEventCreateWithFlags(&evG2a, cudaEventDisableTiming);
        cudaFuncSetAttribute(k_gemm1_mma, cudaFuncAttributeMaxDynamicSharedMemorySize, SM1_TOTAL);
        cudaFuncSetAttribute(k_gemm2_mma, cudaFuncAttributeMaxDynamicSharedMemorySize, SM2_TOTAL);
    }

    // fork: s2 builds CSR; main preps W (merged) + runs GEMM1
    cudaEventRecord(evF, 0);
    cudaStreamWaitEvent(s2, evF, 0);

    k_zero_cnt<<<NBLK, T, 0, s2>>>();
    k_count<<<(EE + T - 1) / T, T, 0, s2>>>(ei);
    k_scan_block<<<NBLK, T, 0, s2>>>();
    k_scan_bsums<<<1, 512, 0, s2>>>();
    k_scan_add<<<NBLK, T, 0, s2>>>();          // finalize + dinv
    k_reorder<<<(EE + T - 1) / T, T, 0, s2>>>(ei);
    cudaEventRecord(evCSR, s2);

    k_prep_w<<<(128 * 128 + 128 * 64 + T - 1) / T, T>>>(W1, W2);
    k_gemm1_mma<<<(NN + 127) / 128, T, SM1_TOTAL>>>(x);

    // join CSR, then pipelined layer-1 aggregation / layer-2 GEMM
    cudaStreamWaitEvent(0, evCSR, 0);
    k_agg1<<<(SPLIT * 32 + T - 1) / T, T>>>(b1, 0, SPLIT);                 // half 0
    cudaEventRecord(evA0, 0);

    // s2: gemm2 on half 0 while main aggregates half 1
    cudaStreamWaitEvent(s2, evA0, 0);
    k_gemm2_mma<<<SPLIT / 128, T, SM2_TOTAL, s2>>>(0);
    cudaEventRecord(evG2a, s2);

    k_agg1<<<((NN - SPLIT) * 32 + T - 1) / T, T>>>(b1, SPLIT, NN);         // half 1
    k_gemm2_mma<<<(NN - SPLIT + 127) / 128, T, SM2_TOTAL>>>(SPLIT);

    // join gemm2 half 0, final aggregation into d_out
    cudaStreamWaitEvent(0, evG2a, 0);
    k_agg2<<<((size_t)NN * 16 + T - 1) / T, T>>>(b2, out);
}